// round 13
// baseline (speedup 1.0000x reference)
#include <cuda_runtime.h>
#include <cstdint>

// ---------------------------------------------------------------------------
// SphericalHarmonicTransform, f32x2-packed: 2 points per thread per iteration.
// Packed (-m,+m) accumulator pairs, fast sqrt/div head, prefetched loads,
// ZI hoisted per distinct (p,q), two-kernel deterministic reduction.
// Replicates the reference's exact (buggy) complex-power recurrence.
// ---------------------------------------------------------------------------

#define NBLK 592
#define NTHR 256
#define NOUT 81

__device__ float g_scratch[NOUT * NBLK];

// ---- compile-time helpers -------------------------------------------------
__host__ __device__ constexpr double dfact(int n) {
    double r = 1.0;
    for (int i = 2; i <= n; ++i) r *= (double)i;
    return r;
}
__host__ __device__ constexpr double csqrt(double x) {
    double g = x > 1.0 ? x : 1.0;
    for (int i = 0; i < 128; ++i) g = 0.5 * (g + x / g);
    return g;
}
constexpr double PI_REF = 3.14159;                    // reference's PI
constexpr float  PIC    = 0.62831853071795864769f;    // pi/RCUT (true pi)

template <int I> struct ic { static constexpr int v = I; };
template <int S, int E, class F>
__device__ __forceinline__ void sfor(F f) {
    if constexpr (S < E) { f(ic<S>{}); sfor<S + 1, E>(f); }
}

// pair index for (l, m>0): l-outer, m = 1..l
__host__ __device__ constexpr int pidx(int l, int m) {
    return l * (l - 1) / 2 + (m - 1);
}

// ---- packed f32x2 wrappers (SASS FFMA2/FMUL2/FADD2) -----------------------
struct f2 { unsigned long long v; };
__device__ __forceinline__ f2 pk2(float lo, float hi) {
    f2 r; asm("mov.b64 %0, {%1, %2};" : "=l"(r.v) : "f"(lo), "f"(hi)); return r;
}
__device__ __forceinline__ void up2(f2 a, float& lo, float& hi) {
    asm("mov.b64 {%0, %1}, %2;" : "=f"(lo), "=f"(hi) : "l"(a.v));
}
__device__ __forceinline__ f2 mul2(f2 a, f2 b) {
    f2 r; asm("mul.rn.f32x2 %0, %1, %2;" : "=l"(r.v) : "l"(a.v), "l"(b.v)); return r;
}
__device__ __forceinline__ f2 add2(f2 a, f2 b) {
    f2 r; asm("add.rn.f32x2 %0, %1, %2;" : "=l"(r.v) : "l"(a.v), "l"(b.v)); return r;
}
__device__ __forceinline__ f2 fma2(f2 a, f2 b, f2 c) {
    f2 r; asm("fma.rn.f32x2 %0, %1, %2, %3;"
              : "=l"(r.v) : "l"(a.v), "l"(b.v), "l"(c.v)); return r;
}

__device__ __forceinline__ void head(float x, float y, float z,
                                     float& cutz, float& inv) {
    const float n2 = fmaf(x, x, fmaf(y, y, z * z));
    const float nm = sqrtf(n2);
    float c = 0.5f * (__cosf(nm * PIC) + 1.0f);
    float s = nm;
    if (nm > 5.0f) c = 0.0f;                 // RCUT
    if (!(nm > 0.0f)) { c = 0.0f; s = 1.0f; }
    inv  = __fdividef(1.0f, s);
    cutz = c * z;
}

__global__ void __launch_bounds__(NTHR)
sht_main(const float* __restrict__ pos, int n)
{
    float acc0[9];                 // m == 0 outputs (index l*l+l)
    f2    accP[36];                // (l, m>0): lo = acc[l*l+l-m], hi = +m
#pragma unroll
    for (int j = 0; j < 9; ++j)  acc0[j] = 0.0f;
#pragma unroll
    for (int j = 0; j < 36; ++j) accP[j].v = 0ull;

    const f2 C_NH = pk2(-0.5f, -0.5f);
    const f2 C_PH = pk2( 0.5f,  0.5f);
    const f2 C_N1 = pk2(-1.0f, -1.0f);

    const int npairs = n >> 1;                        // n is even (4194304)
    const int stride = NBLK * NTHR;

    // First iteration is always valid: NBLK*NTHR = 151552 <= npairs.
    int i = blockIdx.x * NTHR + threadIdx.x;
    const float2* pp = (const float2*)pos + 3 * i;
    float2 v0 = pp[0], v1 = pp[1], v2 = pp[2];

    while (true) {
        // ---- prefetch next iteration's points (covered by this body) ------
        const int inext = i + stride;
        const bool more = inext < npairs;
        float2 w0, w1, w2;
        if (more) {
            const float2* pn = (const float2*)pos + 3 * inext;
            w0 = pn[0]; w1 = pn[1]; w2 = pn[2];
        }

        const float xa = v0.x, ya = v0.y, za = v1.x;
        const float xb = v1.y, yb = v2.x, zb = v2.y;

        float cza, ia, czb, ib;
        head(xa, ya, za, cza, ia);
        head(xb, yb, zb, czb, ib);
        const f2 INV = pk2(ia, ib);

        const f2 X  = pk2(xa, xb);
        const f2 Y  = pk2(ya, yb);
        const f2 ar = mul2(X, C_NH);     // -x/2
        const f2 ai = mul2(Y, C_NH);     // -y/2  (== bi)
        const f2 br = mul2(X, C_PH);     //  x/2
        const f2 nai = mul2(Y, C_PH);    //  y/2 == -ai

        // ---- p1 = powers of (ar, ai), reference's buggy chain -------------
        f2 p1r[9], p1i[9];
        p1r[1] = ar; p1i[1] = ai;
        {
            const f2 t = mul2(ar, ai);
            p1r[2] = fma2(nai, ai, mul2(ar, ar));     // ar^2 - ai^2
            p1i[2] = add2(t, t);                      // 2 ar ai
        }
        {
            f2 cr = ar, ci = ai;
            {   // iter^1 (chain state; NOT equal to p1[2])
                f2 nr = fma2(nai, ci, mul2(ar, cr));
                ci = fma2(ai, nr, mul2(ar, ci));      // uses NEW real
                cr = nr;
            }
            sfor<3, 9>([&](auto K) {
                f2 nr = fma2(nai, ci, mul2(ar, cr));
                ci = fma2(ai, nr, mul2(ar, ci));
                cr = nr;
                p1r[decltype(K)::v] = cr; p1i[decltype(K)::v] = ci;
            });
        }

        // ---- p2 = powers of (br, ai) --------------------------------------
        f2 p2r[5], p2i[5], np2i[5];
        p2r[1] = br;      p2i[1]  = ai;      np2i[1] = nai;
        p2r[2] = p1r[2];  np2i[2] = p1i[2];  p2i[2]  = mul2(p1i[2], C_N1);
        {
            f2 cr = br, ci = ai;
            {   // iter^1
                f2 nr = fma2(nai, ci, mul2(br, cr));
                ci = fma2(ai, nr, mul2(br, ci));
                cr = nr;
            }
            sfor<3, 5>([&](auto K) {
                f2 nr = fma2(nai, ci, mul2(br, cr));
                ci = fma2(ai, nr, mul2(br, ci));
                cr = nr;
                p2r[decltype(K)::v]  = cr;
                p2i[decltype(K)::v]  = ci;
                np2i[decltype(K)::v] = mul2(ci, C_N1);
            });
        }

        f2 sq1[9];
        sfor<1, 9>([&](auto P) {
            constexpr int p = decltype(P)::v;
            sq1[p] = mul2(p1r[p], p1r[p]);
        });

        // ---- hoist ZI per distinct (p,q): q=1..3, p=q+1..8-q (12 values) ---
        f2 ZI[3][8];
        sfor<1, 4>([&](auto Qc) {
            constexpr int q = decltype(Qc)::v;
            sfor<q + 1, 9 - q>([&](auto Pc) {
                constexpr int p = decltype(Pc)::v;
                ZI[q - 1][p] = fma2(p1r[p], p2i[q], mul2(p1i[p], p2r[q]));
            });
        });

        // ---- terms: scalar imm-FFMA sums, packed pair accumulate -----------
        f2 WL = pk2(cza, czb);                        // cut*z * inv^l (l=0)
        sfor<0, 9>([&](auto Lc) {
            constexpr int l = decltype(Lc)::v;
            float wl0, wl1; up2(WL, wl0, wl1);
            const f2 W0 = pk2(wl0, wl0);              // broadcast per l
            const f2 W1 = pk2(wl1, wl1);
            sfor<0, l + 1>([&](auto Mc) {
                constexpr int m    = decltype(Mc)::v;
                constexpr int pmax = (l + m) / 2;
                float sr0 = 0.0f, sr1 = 0.0f, si0 = 0.0f, si1 = 0.0f;
                sfor<m, pmax + 1>([&](auto Pc) {
                    constexpr int p = decltype(Pc)::v;
                    constexpr int q = p - m;
                    constexpr int s = l - p - q;
                    constexpr double kl  = csqrt((2.0 * l + 1.0) / (4.0 * PI_REF));
                    constexpr double ff  = csqrt(dfact(l + m) * dfact(l - m));
                    constexpr double fac = (m == 0) ? 1.0
                        : 1.41421356237309514547 * ((m & 1) ? -1.0 : 1.0);
                    constexpr float c =
                        (float)(kl * ff * fac /
                                (dfact(p) * dfact(q) * dfact(s)));
                    if constexpr (p == 0) {
                        sr0 += c; sr1 += c;           // zr=1, zi=0
                    } else if constexpr (q == 0) {
                        float a0, a1; up2(sq1[p], a0, a1);
                        sr0 = fmaf(a0, c, sr0); sr1 = fmaf(a1, c, sr1);
                        if constexpr (m > 0) {
                            float b0, b1; up2(p1i[p], b0, b1);
                            si0 = fmaf(b0, c, si0); si1 = fmaf(b1, c, si1);
                        }
                    } else {
                        const f2 zr = fma2(np2i[q], p2i[q], sq1[p]);
                        float a0, a1; up2(zr, a0, a1);
                        sr0 = fmaf(a0, c, sr0); sr1 = fmaf(a1, c, sr1);
                        if constexpr (m > 0) {
                            float b0, b1; up2(ZI[q - 1][p], b0, b1);
                            si0 = fmaf(b0, c, si0); si1 = fmaf(b1, c, si1);
                        }
                    }
                });
                if constexpr (m == 0) {
                    acc0[l] = fmaf(sr1, wl1, fmaf(sr0, wl0, acc0[l]));
                } else {
                    constexpr int pi = pidx(l, m);
                    // lo: si1*wl1 + (si0*wl0 + acc_lo)  (== -m output)
                    // hi: sr1*wl1 + (sr0*wl0 + acc_hi)  (== +m output)
                    accP[pi] = fma2(pk2(si1, sr1), W1,
                               fma2(pk2(si0, sr0), W0, accP[pi]));
                }
            });
            WL = mul2(WL, INV);
        });

        if (!more) break;
        v0 = w0; v1 = w1; v2 = w2;
        i = inext;
    }

    // ---- unpack accumulators -----------------------------------------------
    float acc[NOUT];
    sfor<0, 9>([&](auto Lc) {
        constexpr int l = decltype(Lc)::v;
        acc[l * l + l] = acc0[l];
        sfor<1, l + 1>([&](auto Mc) {
            constexpr int m  = decltype(Mc)::v;
            constexpr int pi = pidx(l, m);
            float lo, hi; up2(accP[pi], lo, hi);
            acc[l * l + l - m] = lo;
            acc[l * l + l + m] = hi;
        });
    });

    // ---- block reduction ---------------------------------------------------
    __shared__ float sred[NOUT * 8];
    const int lane = threadIdx.x & 31;
    const int warp = threadIdx.x >> 5;
#pragma unroll
    for (int j = 0; j < NOUT; ++j) {
        float v = acc[j];
        v += __shfl_down_sync(0xffffffffu, v, 16);
        v += __shfl_down_sync(0xffffffffu, v, 8);
        v += __shfl_down_sync(0xffffffffu, v, 4);
        v += __shfl_down_sync(0xffffffffu, v, 2);
        v += __shfl_down_sync(0xffffffffu, v, 1);
        if (lane == 0) sred[j * 8 + warp] = v;
    }
    __syncthreads();
    if (threadIdx.x < NOUT) {
        float s = 0.0f;
#pragma unroll
        for (int w = 0; w < 8; ++w) s += sred[threadIdx.x * 8 + w];
        g_scratch[threadIdx.x * NBLK + blockIdx.x] = s;
    }
}

// Deterministic final reduction: one block per output element.
__global__ void __launch_bounds__(256)
sht_reduce(float* __restrict__ out)
{
    const int j = blockIdx.x;
    float v = 0.0f;
    for (int t = threadIdx.x; t < NBLK; t += 256)
        v += g_scratch[j * NBLK + t];

    v += __shfl_down_sync(0xffffffffu, v, 16);
    v += __shfl_down_sync(0xffffffffu, v, 8);
    v += __shfl_down_sync(0xffffffffu, v, 4);
    v += __shfl_down_sync(0xffffffffu, v, 2);
    v += __shfl_down_sync(0xffffffffu, v, 1);

    __shared__ float sw[8];
    const int lane = threadIdx.x & 31;
    const int warp = threadIdx.x >> 5;
    if (lane == 0) sw[warp] = v;
    __syncthreads();
    if (threadIdx.x == 0) {
        float s = 0.0f;
#pragma unroll
        for (int w = 0; w < 8; ++w) s += sw[w];
        out[j] = s;
    }
}

extern "C" void kernel_launch(void* const* d_in, const int* in_sizes, int n_in,
                              void* d_out, int out_size)
{
    const float* pos = (const float*)d_in[0];
    const int n = in_sizes[0] / 3;
    sht_main<<<NBLK, NTHR>>>(pos, n);
    sht_reduce<<<NOUT, 256>>>((float*)d_out);
}

// round 14
// speedup vs baseline: 1.1411x; 1.1411x over previous
#include <cuda_runtime.h>
#include <cstdint>

// ---------------------------------------------------------------------------
// SphericalHarmonicTransform, f32x2-packed: 2 points per thread per iteration.
// Scalar accumulators, fast sqrt/div head, prefetched loads, ZI hoisted per
// distinct (p,q), ONE-WAVE launch (148 CTAs), two-kernel deterministic
// reduction. Replicates the reference's exact (buggy) complex-power recurrence.
// ---------------------------------------------------------------------------

#define NBLK 148            // exactly one wave: 1 CTA/SM on 148 SMs
#define NTHR 256
#define NOUT 81

__device__ float g_scratch[NOUT * NBLK];

// ---- compile-time helpers -------------------------------------------------
__host__ __device__ constexpr double dfact(int n) {
    double r = 1.0;
    for (int i = 2; i <= n; ++i) r *= (double)i;
    return r;
}
__host__ __device__ constexpr double csqrt(double x) {
    double g = x > 1.0 ? x : 1.0;
    for (int i = 0; i < 128; ++i) g = 0.5 * (g + x / g);
    return g;
}
constexpr double PI_REF = 3.14159;                    // reference's PI
constexpr float  PIC    = 0.62831853071795864769f;    // pi/RCUT (true pi)

template <int I> struct ic { static constexpr int v = I; };
template <int S, int E, class F>
__device__ __forceinline__ void sfor(F f) {
    if constexpr (S < E) { f(ic<S>{}); sfor<S + 1, E>(f); }
}

// ---- packed f32x2 wrappers (SASS FFMA2/FMUL2/FADD2) -----------------------
struct f2 { unsigned long long v; };
__device__ __forceinline__ f2 pk2(float lo, float hi) {
    f2 r; asm("mov.b64 %0, {%1, %2};" : "=l"(r.v) : "f"(lo), "f"(hi)); return r;
}
__device__ __forceinline__ void up2(f2 a, float& lo, float& hi) {
    asm("mov.b64 {%0, %1}, %2;" : "=f"(lo), "=f"(hi) : "l"(a.v));
}
__device__ __forceinline__ f2 mul2(f2 a, f2 b) {
    f2 r; asm("mul.rn.f32x2 %0, %1, %2;" : "=l"(r.v) : "l"(a.v), "l"(b.v)); return r;
}
__device__ __forceinline__ f2 add2(f2 a, f2 b) {
    f2 r; asm("add.rn.f32x2 %0, %1, %2;" : "=l"(r.v) : "l"(a.v), "l"(b.v)); return r;
}
__device__ __forceinline__ f2 fma2(f2 a, f2 b, f2 c) {
    f2 r; asm("fma.rn.f32x2 %0, %1, %2, %3;"
              : "=l"(r.v) : "l"(a.v), "l"(b.v), "l"(c.v)); return r;
}

__device__ __forceinline__ void head(float x, float y, float z,
                                     float& cutz, float& inv) {
    const float n2 = fmaf(x, x, fmaf(y, y, z * z));
    const float nm = sqrtf(n2);
    float c = 0.5f * (__cosf(nm * PIC) + 1.0f);
    float s = nm;
    if (nm > 5.0f) c = 0.0f;                 // RCUT
    if (!(nm > 0.0f)) { c = 0.0f; s = 1.0f; }
    inv  = __fdividef(1.0f, s);
    cutz = c * z;
}

__global__ void __launch_bounds__(NTHR)
sht_main(const float* __restrict__ pos, int n)
{
    float acc[NOUT];
#pragma unroll
    for (int j = 0; j < NOUT; ++j) acc[j] = 0.0f;

    const f2 C_NH = pk2(-0.5f, -0.5f);
    const f2 C_PH = pk2( 0.5f,  0.5f);
    const f2 C_N1 = pk2(-1.0f, -1.0f);

    const int npairs = n >> 1;                        // n is even (4194304)
    const int stride = NBLK * NTHR;

    // First iteration is always valid: NBLK*NTHR = 37888 <= npairs.
    int i = blockIdx.x * NTHR + threadIdx.x;
    const float2* pp = (const float2*)pos + 3 * i;
    float2 v0 = pp[0], v1 = pp[1], v2 = pp[2];

    while (true) {
        // ---- prefetch next iteration's points (covered by this body) ------
        const int inext = i + stride;
        const bool more = inext < npairs;
        float2 w0, w1, w2;
        if (more) {
            const float2* pn = (const float2*)pos + 3 * inext;
            w0 = pn[0]; w1 = pn[1]; w2 = pn[2];
        }

        const float xa = v0.x, ya = v0.y, za = v1.x;
        const float xb = v1.y, yb = v2.x, zb = v2.y;

        float cza, ia, czb, ib;
        head(xa, ya, za, cza, ia);
        head(xb, yb, zb, czb, ib);
        const f2 INV = pk2(ia, ib);

        const f2 X  = pk2(xa, xb);
        const f2 Y  = pk2(ya, yb);
        const f2 ar = mul2(X, C_NH);     // -x/2
        const f2 ai = mul2(Y, C_NH);     // -y/2  (== bi)
        const f2 br = mul2(X, C_PH);     //  x/2
        const f2 nai = mul2(Y, C_PH);    //  y/2 == -ai

        // ---- p1 = powers of (ar, ai), reference's buggy chain -------------
        f2 p1r[9], p1i[9];
        p1r[1] = ar; p1i[1] = ai;
        {
            const f2 t = mul2(ar, ai);
            p1r[2] = fma2(nai, ai, mul2(ar, ar));     // ar^2 - ai^2
            p1i[2] = add2(t, t);                      // 2 ar ai
        }
        {
            f2 cr = ar, ci = ai;
            {   // iter^1 (chain state; NOT equal to p1[2])
                f2 nr = fma2(nai, ci, mul2(ar, cr));
                ci = fma2(ai, nr, mul2(ar, ci));      // uses NEW real
                cr = nr;
            }
            sfor<3, 9>([&](auto K) {
                f2 nr = fma2(nai, ci, mul2(ar, cr));
                ci = fma2(ai, nr, mul2(ar, ci));
                cr = nr;
                p1r[decltype(K)::v] = cr; p1i[decltype(K)::v] = ci;
            });
        }

        // ---- p2 = powers of (br, ai) --------------------------------------
        f2 p2r[5], p2i[5], np2i[5];
        p2r[1] = br;      p2i[1]  = ai;      np2i[1] = nai;
        p2r[2] = p1r[2];  np2i[2] = p1i[2];  p2i[2]  = mul2(p1i[2], C_N1);
        {
            f2 cr = br, ci = ai;
            {   // iter^1
                f2 nr = fma2(nai, ci, mul2(br, cr));
                ci = fma2(ai, nr, mul2(br, ci));
                cr = nr;
            }
            sfor<3, 5>([&](auto K) {
                f2 nr = fma2(nai, ci, mul2(br, cr));
                ci = fma2(ai, nr, mul2(br, ci));
                cr = nr;
                p2r[decltype(K)::v]  = cr;
                p2i[decltype(K)::v]  = ci;
                np2i[decltype(K)::v] = mul2(ci, C_N1);
            });
        }

        f2 sq1[9];
        sfor<1, 9>([&](auto P) {
            constexpr int p = decltype(P)::v;
            sq1[p] = mul2(p1r[p], p1r[p]);
        });

        // ---- hoist ZI per distinct (p,q): q=1..3, p=q+1..8-q (12 values) ---
        f2 ZI[3][8];
        sfor<1, 4>([&](auto Qc) {
            constexpr int q = decltype(Qc)::v;
            sfor<q + 1, 9 - q>([&](auto Pc) {
                constexpr int p = decltype(Pc)::v;
                ZI[q - 1][p] = fma2(p1r[p], p2i[q], mul2(p1i[p], p2r[q]));
            });
        });

        // ---- terms: scalar imm-FFMA sums, packed zr, scalar accumulate -----
        f2 WL = pk2(cza, czb);                        // cut*z * inv^l (l=0)
        sfor<0, 9>([&](auto Lc) {
            constexpr int l = decltype(Lc)::v;
            float wl0, wl1; up2(WL, wl0, wl1);
            sfor<0, l + 1>([&](auto Mc) {
                constexpr int m    = decltype(Mc)::v;
                constexpr int pmax = (l + m) / 2;
                float sr0 = 0.0f, sr1 = 0.0f, si0 = 0.0f, si1 = 0.0f;
                sfor<m, pmax + 1>([&](auto Pc) {
                    constexpr int p = decltype(Pc)::v;
                    constexpr int q = p - m;
                    constexpr int s = l - p - q;
                    constexpr double kl  = csqrt((2.0 * l + 1.0) / (4.0 * PI_REF));
                    constexpr double ff  = csqrt(dfact(l + m) * dfact(l - m));
                    constexpr double fac = (m == 0) ? 1.0
                        : 1.41421356237309514547 * ((m & 1) ? -1.0 : 1.0);
                    constexpr float c =
                        (float)(kl * ff * fac /
                                (dfact(p) * dfact(q) * dfact(s)));
                    if constexpr (p == 0) {
                        sr0 += c; sr1 += c;           // zr=1, zi=0
                    } else if constexpr (q == 0) {
                        float a0, a1; up2(sq1[p], a0, a1);
                        sr0 = fmaf(a0, c, sr0); sr1 = fmaf(a1, c, sr1);
                        if constexpr (m > 0) {
                            float b0, b1; up2(p1i[p], b0, b1);
                            si0 = fmaf(b0, c, si0); si1 = fmaf(b1, c, si1);
                        }
                    } else {
                        const f2 zr = fma2(np2i[q], p2i[q], sq1[p]);
                        float a0, a1; up2(zr, a0, a1);
                        sr0 = fmaf(a0, c, sr0); sr1 = fmaf(a1, c, sr1);
                        if constexpr (m > 0) {
                            float b0, b1; up2(ZI[q - 1][p], b0, b1);
                            si0 = fmaf(b0, c, si0); si1 = fmaf(b1, c, si1);
                        }
                    }
                });
                if constexpr (m == 0) {
                    acc[l * l + l] =
                        fmaf(sr1, wl1, fmaf(sr0, wl0, acc[l * l + l]));
                } else {
                    acc[l * l + l - m] =
                        fmaf(si1, wl1, fmaf(si0, wl0, acc[l * l + l - m]));
                    acc[l * l + l + m] =
                        fmaf(sr1, wl1, fmaf(sr0, wl0, acc[l * l + l + m]));
                }
            });
            WL = mul2(WL, INV);
        });

        if (!more) break;
        v0 = w0; v1 = w1; v2 = w2;
        i = inext;
    }

    // ---- block reduction ---------------------------------------------------
    __shared__ float sred[NOUT * 8];
    const int lane = threadIdx.x & 31;
    const int warp = threadIdx.x >> 5;
#pragma unroll
    for (int j = 0; j < NOUT; ++j) {
        float v = acc[j];
        v += __shfl_down_sync(0xffffffffu, v, 16);
        v += __shfl_down_sync(0xffffffffu, v, 8);
        v += __shfl_down_sync(0xffffffffu, v, 4);
        v += __shfl_down_sync(0xffffffffu, v, 2);
        v += __shfl_down_sync(0xffffffffu, v, 1);
        if (lane == 0) sred[j * 8 + warp] = v;
    }
    __syncthreads();
    if (threadIdx.x < NOUT) {
        float s = 0.0f;
#pragma unroll
        for (int w = 0; w < 8; ++w) s += sred[threadIdx.x * 8 + w];
        g_scratch[threadIdx.x * NBLK + blockIdx.x] = s;
    }
}

// Deterministic final reduction: one block per output element.
__global__ void __launch_bounds__(256)
sht_reduce(float* __restrict__ out)
{
    const int j = blockIdx.x;
    float v = 0.0f;
    for (int t = threadIdx.x; t < NBLK; t += 256)
        v += g_scratch[j * NBLK + t];

    v += __shfl_down_sync(0xffffffffu, v, 16);
    v += __shfl_down_sync(0xffffffffu, v, 8);
    v += __shfl_down_sync(0xffffffffu, v, 4);
    v += __shfl_down_sync(0xffffffffu, v, 2);
    v += __shfl_down_sync(0xffffffffu, v, 1);

    __shared__ float sw[8];
    const int lane = threadIdx.x & 31;
    const int warp = threadIdx.x >> 5;
    if (lane == 0) sw[warp] = v;
    __syncthreads();
    if (threadIdx.x == 0) {
        float s = 0.0f;
#pragma unroll
        for (int w = 0; w < 8; ++w) s += sw[w];
        out[j] = s;
    }
}

extern "C" void kernel_launch(void* const* d_in, const int* in_sizes, int n_in,
                              void* d_out, int out_size)
{
    const float* pos = (const float*)d_in[0];
    const int n = in_sizes[0] / 3;
    sht_main<<<NBLK, NTHR>>>(pos, n);
    sht_reduce<<<NOUT, 256>>>((float*)d_out);
}

// round 15
// speedup vs baseline: 1.2656x; 1.1091x over previous
#include <cuda_runtime.h>
#include <cstdint>

// ---------------------------------------------------------------------------
// SphericalHarmonicTransform, f32x2-packed: 2 points per thread per iteration.
// Scalar accumulators, raw MUFU.RSQ head (rsqrt.approx — NOT __frsqrt_rn),
// prefetched loads, ZI hoisted per distinct (p,q), ONE-WAVE launch (148 CTAs),
// two-kernel deterministic reduction.
// Replicates the reference's exact (buggy) complex-power recurrence.
// ---------------------------------------------------------------------------

#define NBLK 148            // exactly one wave: 1 CTA/SM on 148 SMs
#define NTHR 256
#define NOUT 81

__device__ float g_scratch[NOUT * NBLK];

// ---- compile-time helpers -------------------------------------------------
__host__ __device__ constexpr double dfact(int n) {
    double r = 1.0;
    for (int i = 2; i <= n; ++i) r *= (double)i;
    return r;
}
__host__ __device__ constexpr double csqrt(double x) {
    double g = x > 1.0 ? x : 1.0;
    for (int i = 0; i < 128; ++i) g = 0.5 * (g + x / g);
    return g;
}
constexpr double PI_REF = 3.14159;                    // reference's PI
constexpr float  PIC    = 0.62831853071795864769f;    // pi/RCUT (true pi)

template <int I> struct ic { static constexpr int v = I; };
template <int S, int E, class F>
__device__ __forceinline__ void sfor(F f) {
    if constexpr (S < E) { f(ic<S>{}); sfor<S + 1, E>(f); }
}

// ---- packed f32x2 wrappers (SASS FFMA2/FMUL2/FADD2) -----------------------
struct f2 { unsigned long long v; };
__device__ __forceinline__ f2 pk2(float lo, float hi) {
    f2 r; asm("mov.b64 %0, {%1, %2};" : "=l"(r.v) : "f"(lo), "f"(hi)); return r;
}
__device__ __forceinline__ void up2(f2 a, float& lo, float& hi) {
    asm("mov.b64 {%0, %1}, %2;" : "=f"(lo), "=f"(hi) : "l"(a.v));
}
__device__ __forceinline__ f2 mul2(f2 a, f2 b) {
    f2 r; asm("mul.rn.f32x2 %0, %1, %2;" : "=l"(r.v) : "l"(a.v), "l"(b.v)); return r;
}
__device__ __forceinline__ f2 add2(f2 a, f2 b) {
    f2 r; asm("add.rn.f32x2 %0, %1, %2;" : "=l"(r.v) : "l"(a.v), "l"(b.v)); return r;
}
__device__ __forceinline__ f2 fma2(f2 a, f2 b, f2 c) {
    f2 r; asm("fma.rn.f32x2 %0, %1, %2, %3;"
              : "=l"(r.v) : "l"(a.v), "l"(b.v), "l"(c.v)); return r;
}

__device__ __forceinline__ void head(float x, float y, float z,
                                     float& cutz, float& inv) {
    const float n2 = fmaf(x, x, fmaf(y, y, z * z));
    float rn;                                 // bare MUFU.RSQ (approx)
    asm("rsqrt.approx.f32 %0, %1;" : "=f"(rn) : "f"(n2));
    const float nm = n2 * rn;                 // norm (NaN if n2 == 0)
    float c = 0.5f * (__cosf(nm * PIC) + 1.0f);
    if (nm > 5.0f) c = 0.0f;                  // RCUT (false for NaN)
    if (!(n2 > 0.0f)) { c = 0.0f; rn = 1.0f; }
    inv  = rn;
    cutz = c * z;
}

__global__ void __launch_bounds__(NTHR)
sht_main(const float* __restrict__ pos, int n)
{
    float acc[NOUT];
#pragma unroll
    for (int j = 0; j < NOUT; ++j) acc[j] = 0.0f;

    const f2 C_NH = pk2(-0.5f, -0.5f);
    const f2 C_PH = pk2( 0.5f,  0.5f);
    const f2 C_N1 = pk2(-1.0f, -1.0f);

    const int npairs = n >> 1;                        // n is even (4194304)
    const int stride = NBLK * NTHR;

    // First iteration is always valid: NBLK*NTHR = 37888 <= npairs.
    int i = blockIdx.x * NTHR + threadIdx.x;
    const float2* pp = (const float2*)pos + 3 * i;
    float2 v0 = pp[0], v1 = pp[1], v2 = pp[2];

    while (true) {
        // ---- prefetch next iteration's points (covered by this body) ------
        const int inext = i + stride;
        const bool more = inext < npairs;
        float2 w0, w1, w2;
        if (more) {
            const float2* pn = (const float2*)pos + 3 * inext;
            w0 = pn[0]; w1 = pn[1]; w2 = pn[2];
        }

        const float xa = v0.x, ya = v0.y, za = v1.x;
        const float xb = v1.y, yb = v2.x, zb = v2.y;

        float cza, ia, czb, ib;
        head(xa, ya, za, cza, ia);
        head(xb, yb, zb, czb, ib);
        const f2 INV = pk2(ia, ib);

        const f2 X  = pk2(xa, xb);
        const f2 Y  = pk2(ya, yb);
        const f2 ar = mul2(X, C_NH);     // -x/2
        const f2 ai = mul2(Y, C_NH);     // -y/2  (== bi)
        const f2 br = mul2(X, C_PH);     //  x/2
        const f2 nai = mul2(Y, C_PH);    //  y/2 == -ai

        // ---- p1 = powers of (ar, ai), reference's buggy chain -------------
        f2 p1r[9], p1i[9];
        p1r[1] = ar; p1i[1] = ai;
        {
            const f2 t = mul2(ar, ai);
            p1r[2] = fma2(nai, ai, mul2(ar, ar));     // ar^2 - ai^2
            p1i[2] = add2(t, t);                      // 2 ar ai
        }
        {
            f2 cr = ar, ci = ai;
            {   // iter^1 (chain state; NOT equal to p1[2])
                f2 nr = fma2(nai, ci, mul2(ar, cr));
                ci = fma2(ai, nr, mul2(ar, ci));      // uses NEW real
                cr = nr;
            }
            sfor<3, 9>([&](auto K) {
                f2 nr = fma2(nai, ci, mul2(ar, cr));
                ci = fma2(ai, nr, mul2(ar, ci));
                cr = nr;
                p1r[decltype(K)::v] = cr; p1i[decltype(K)::v] = ci;
            });
        }

        // ---- p2 = powers of (br, ai) --------------------------------------
        f2 p2r[5], p2i[5], np2i[5];
        p2r[1] = br;      p2i[1]  = ai;      np2i[1] = nai;
        p2r[2] = p1r[2];  np2i[2] = p1i[2];  p2i[2]  = mul2(p1i[2], C_N1);
        {
            f2 cr = br, ci = ai;
            {   // iter^1
                f2 nr = fma2(nai, ci, mul2(br, cr));
                ci = fma2(ai, nr, mul2(br, ci));
                cr = nr;
            }
            sfor<3, 5>([&](auto K) {
                f2 nr = fma2(nai, ci, mul2(br, cr));
                ci = fma2(ai, nr, mul2(br, ci));
                cr = nr;
                p2r[decltype(K)::v]  = cr;
                p2i[decltype(K)::v]  = ci;
                np2i[decltype(K)::v] = mul2(ci, C_N1);
            });
        }

        f2 sq1[9];
        sfor<1, 9>([&](auto P) {
            constexpr int p = decltype(P)::v;
            sq1[p] = mul2(p1r[p], p1r[p]);
        });

        // ---- hoist ZI per distinct (p,q): q=1..3, p=q+1..8-q (12 values) ---
        f2 ZI[3][8];
        sfor<1, 4>([&](auto Qc) {
            constexpr int q = decltype(Qc)::v;
            sfor<q + 1, 9 - q>([&](auto Pc) {
                constexpr int p = decltype(Pc)::v;
                ZI[q - 1][p] = fma2(p1r[p], p2i[q], mul2(p1i[p], p2r[q]));
            });
        });

        // ---- terms: scalar imm-FFMA sums, packed zr, scalar accumulate -----
        f2 WL = pk2(cza, czb);                        // cut*z * inv^l (l=0)
        sfor<0, 9>([&](auto Lc) {
            constexpr int l = decltype(Lc)::v;
            float wl0, wl1; up2(WL, wl0, wl1);
            sfor<0, l + 1>([&](auto Mc) {
                constexpr int m    = decltype(Mc)::v;
                constexpr int pmax = (l + m) / 2;
                float sr0 = 0.0f, sr1 = 0.0f, si0 = 0.0f, si1 = 0.0f;
                sfor<m, pmax + 1>([&](auto Pc) {
                    constexpr int p = decltype(Pc)::v;
                    constexpr int q = p - m;
                    constexpr int s = l - p - q;
                    constexpr double kl  = csqrt((2.0 * l + 1.0) / (4.0 * PI_REF));
                    constexpr double ff  = csqrt(dfact(l + m) * dfact(l - m));
                    constexpr double fac = (m == 0) ? 1.0
                        : 1.41421356237309514547 * ((m & 1) ? -1.0 : 1.0);
                    constexpr float c =
                        (float)(kl * ff * fac /
                                (dfact(p) * dfact(q) * dfact(s)));
                    if constexpr (p == 0) {
                        sr0 += c; sr1 += c;           // zr=1, zi=0
                    } else if constexpr (q == 0) {
                        float a0, a1; up2(sq1[p], a0, a1);
                        sr0 = fmaf(a0, c, sr0); sr1 = fmaf(a1, c, sr1);
                        if constexpr (m > 0) {
                            float b0, b1; up2(p1i[p], b0, b1);
                            si0 = fmaf(b0, c, si0); si1 = fmaf(b1, c, si1);
                        }
                    } else {
                        const f2 zr = fma2(np2i[q], p2i[q], sq1[p]);
                        float a0, a1; up2(zr, a0, a1);
                        sr0 = fmaf(a0, c, sr0); sr1 = fmaf(a1, c, sr1);
                        if constexpr (m > 0) {
                            float b0, b1; up2(ZI[q - 1][p], b0, b1);
                            si0 = fmaf(b0, c, si0); si1 = fmaf(b1, c, si1);
                        }
                    }
                });
                if constexpr (m == 0) {
                    acc[l * l + l] =
                        fmaf(sr1, wl1, fmaf(sr0, wl0, acc[l * l + l]));
                } else {
                    acc[l * l + l - m] =
                        fmaf(si1, wl1, fmaf(si0, wl0, acc[l * l + l - m]));
                    acc[l * l + l + m] =
                        fmaf(sr1, wl1, fmaf(sr0, wl0, acc[l * l + l + m]));
                }
            });
            WL = mul2(WL, INV);
        });

        if (!more) break;
        v0 = w0; v1 = w1; v2 = w2;
        i = inext;
    }

    // ---- block reduction ---------------------------------------------------
    __shared__ float sred[NOUT * 8];
    const int lane = threadIdx.x & 31;
    const int warp = threadIdx.x >> 5;
#pragma unroll
    for (int j = 0; j < NOUT; ++j) {
        float v = acc[j];
        v += __shfl_down_sync(0xffffffffu, v, 16);
        v += __shfl_down_sync(0xffffffffu, v, 8);
        v += __shfl_down_sync(0xffffffffu, v, 4);
        v += __shfl_down_sync(0xffffffffu, v, 2);
        v += __shfl_down_sync(0xffffffffu, v, 1);
        if (lane == 0) sred[j * 8 + warp] = v;
    }
    __syncthreads();
    if (threadIdx.x < NOUT) {
        float s = 0.0f;
#pragma unroll
        for (int w = 0; w < 8; ++w) s += sred[threadIdx.x * 8 + w];
        g_scratch[threadIdx.x * NBLK + blockIdx.x] = s;
    }
}

// Deterministic final reduction: one block per output element.
__global__ void __launch_bounds__(256)
sht_reduce(float* __restrict__ out)
{
    const int j = blockIdx.x;
    float v = 0.0f;
    for (int t = threadIdx.x; t < NBLK; t += 256)
        v += g_scratch[j * NBLK + t];

    v += __shfl_down_sync(0xffffffffu, v, 16);
    v += __shfl_down_sync(0xffffffffu, v, 8);
    v += __shfl_down_sync(0xffffffffu, v, 4);
    v += __shfl_down_sync(0xffffffffu, v, 2);
    v += __shfl_down_sync(0xffffffffu, v, 1);

    __shared__ float sw[8];
    const int lane = threadIdx.x & 31;
    const int warp = threadIdx.x >> 5;
    if (lane == 0) sw[warp] = v;
    __syncthreads();
    if (threadIdx.x == 0) {
        float s = 0.0f;
#pragma unroll
        for (int w = 0; w < 8; ++w) s += sw[w];
        out[j] = s;
    }
}

extern "C" void kernel_launch(void* const* d_in, const int* in_sizes, int n_in,
                              void* d_out, int out_size)
{
    const float* pos = (const float*)d_in[0];
    const int n = in_sizes[0] / 3;
    sht_main<<<NBLK, NTHR>>>(pos, n);
    sht_reduce<<<NOUT, 256>>>((float*)d_out);
}